// round 9
// baseline (speedup 1.0000x reference)
#include <cuda_runtime.h>
#include <cuda_bf16.h>
#include <cuda.h>
#include <cstdint>

#define H    128
#define TM   128
#define NTHR 256
#define SA   136    // bf16 elem stride, A tiles  (272B = 4-bank offset/row)
#define SB   136    // bf16 elem stride, B tiles
#define SF   136    // f32 elem stride, msg staging

// ---------------- device scratch (allocation-free) ----------------
__device__ float g_agg[50048 * H];
__device__ float g_P[50048 * H];    // x @ We1[0:128]
__device__ float g_Q[50048 * H];    // x @ We1[128:256]

// ---------------- helpers ----------------
__device__ __forceinline__ uint32_t smem_u32(const void* p) {
    uint32_t a;
    asm("{ .reg .u64 t; cvta.to.shared.u64 t, %1; cvt.u32.u64 %0, t; }" : "=r"(a) : "l"(p));
    return a;
}
__device__ __forceinline__ void red_add_v4(float* addr, float a, float b, float c, float d) {
    asm volatile("red.global.add.v4.f32 [%0], {%1,%2,%3,%4};"
                 :: "l"(addr), "f"(a), "f"(b), "f"(c), "f"(d) : "memory");
}
__device__ __forceinline__ uint32_t pack2(float a, float b) {
    __nv_bfloat16 ha = __float2bfloat16(a), hb = __float2bfloat16(b);
    return (uint32_t)__bfloat16_as_ushort(ha) | ((uint32_t)__bfloat16_as_ushort(hb) << 16);
}
__device__ __forceinline__ float bf_hi(float v) {
    return __bfloat162float(__float2bfloat16(v));
}

#define LDM_X4(d, a) \
    asm volatile("ldmatrix.sync.aligned.m8n8.x4.shared.b16 {%0,%1,%2,%3}, [%4];" \
        : "=r"((d)[0]), "=r"((d)[1]), "=r"((d)[2]), "=r"((d)[3]) : "r"(a))
#define LDM_X2T(d, a) \
    asm volatile("ldmatrix.sync.aligned.m8n8.x2.trans.shared.b16 {%0,%1}, [%2];" \
        : "=r"((d)[0]), "=r"((d)[1]) : "r"(a))
#define MMA_BF16(d, a, b) \
    asm volatile("mma.sync.aligned.m16n8k16.row.col.f32.bf16.bf16.f32 " \
        "{%0,%1,%2,%3}, {%4,%5,%6,%7}, {%8,%9}, {%0,%1,%2,%3};" \
        : "+f"((d)[0]), "+f"((d)[1]), "+f"((d)[2]), "+f"((d)[3]) \
        : "r"((a)[0]), "r"((a)[1]), "r"((a)[2]), "r"((a)[3]), "r"((b)[0]), "r"((b)[1]))

// ---------------- small kernels ----------------
__global__ void zero_agg_kernel(int n4) {
    int i = blockIdx.x * blockDim.x + threadIdx.x;
    if (i < n4) ((float4*)g_agg)[i] = make_float4(0.f, 0.f, 0.f, 0.f);
}

// ---------------------------------------------------------------------------
// prep_pq: P = x @ We1[0:128,:],  Q = x @ We1[128:256,:]  (fp32, proven)
// ---------------------------------------------------------------------------
#define KC 16
__global__ void __launch_bounds__(NTHR, 2)
prep_pq_kernel(const float* __restrict__ x, const float* __restrict__ We1, int nN)
{
    extern __shared__ float sm[];
    float* Bs = sm;                 // [KC][H]
    float* As = sm + KC * H;        // [KC][TM]

    const int tid = threadIdx.x;
    const int tx  = tid & 15;
    const int ty  = tid >> 4;
    const int n0  = blockIdx.x * TM;

    const float* W = We1 + (size_t)(blockIdx.y * H) * H;
    float* outbuf  = blockIdx.y ? g_Q : g_P;

    const int le = tid >> 1;
    const int lh = (tid & 1) * 8;
    const float* aX = x + (size_t)min(n0 + le, nN - 1) * H;

    const int bk = tid >> 4;
    const int bh = (tid & 15) * 8;

    float acc[8][8];
    #pragma unroll
    for (int i = 0; i < 8; i++)
        #pragma unroll
        for (int j = 0; j < 8; j++) acc[i][j] = 0.f;

    for (int kc = 0; kc < 8; kc++) {
        const int k0 = kc * KC;
        float4 a0 = *(const float4*)(aX + k0 + lh);
        float4 a1 = *(const float4*)(aX + k0 + lh + 4);
        const float* wrow = W + (size_t)(k0 + bk) * H + bh;
        float4 b0 = *(const float4*)(wrow);
        float4 b1 = *(const float4*)(wrow + 4);
        __syncthreads();
        As[(lh + 0) * TM + le] = a0.x; As[(lh + 1) * TM + le] = a0.y;
        As[(lh + 2) * TM + le] = a0.z; As[(lh + 3) * TM + le] = a0.w;
        As[(lh + 4) * TM + le] = a1.x; As[(lh + 5) * TM + le] = a1.y;
        As[(lh + 6) * TM + le] = a1.z; As[(lh + 7) * TM + le] = a1.w;
        *(float4*)&Bs[bk * H + bh]     = b0;
        *(float4*)&Bs[bk * H + bh + 4] = b1;
        __syncthreads();
        #pragma unroll
        for (int kk = 0; kk < KC; kk++) {
            float af[8], bf[8];
            *(float4*)&af[0] = *(const float4*)&As[kk * TM + ty * 8];
            *(float4*)&af[4] = *(const float4*)&As[kk * TM + ty * 8 + 4];
            *(float4*)&bf[0] = *(const float4*)&Bs[kk * H + tx * 8];
            *(float4*)&bf[4] = *(const float4*)&Bs[kk * H + tx * 8 + 4];
            #pragma unroll
            for (int i = 0; i < 8; i++)
                #pragma unroll
                for (int j = 0; j < 8; j++)
                    acc[i][j] = fmaf(af[i], bf[j], acc[i][j]);
        }
    }

    #pragma unroll
    for (int i = 0; i < 8; i++) {
        const int r = ty * 8 + i;
        if (n0 + r < nN) {
            float* dst = outbuf + (size_t)(n0 + r) * H + tx * 8;
            *(float4*)(dst)     = make_float4(acc[i][0], acc[i][1], acc[i][2], acc[i][3]);
            *(float4*)(dst + 4) = make_float4(acc[i][4], acc[i][5], acc[i][6], acc[i][7]);
        }
    }
}

// ---------------- SMEM layout for edge kernel ----------------
#define OFF_A_HI  0                      // [128][SA] bf16 = 34816 B
#define OFF_A_LO  34816                  // [128][SA] bf16
#define OFF_B_HI  69632                  // [64][SB]  bf16 = 17408 B
#define OFF_B_LO  87040
#define OFF_ROWI  104448
#define OFF_COLI  104960
#define EDGE_SMEM 105472

// ---------------------------------------------------------------------------
// Edge pass (HMMA bf16x3):
//   stage1: hidden = relu( ea @ We1_c + P[row] + Q[col] + b1 )
//   stage2: msg    = hidden @ We2 + b2 -> red.add.v4 scatter into g_agg[col]
// Block = 128 edges. 8 warps, warp tile 32x64. K chunked at 64.
// ---------------------------------------------------------------------------
__global__ void __launch_bounds__(NTHR, 2)
edge_kernel(const float* __restrict__ ea, const int* __restrict__ eidx,
            const float* __restrict__ We1, const float* __restrict__ be1,
            const float* __restrict__ We2, const float* __restrict__ be2,
            int nE)
{
    extern __shared__ char smraw[];
    int* rowi = (int*)(smraw + OFF_ROWI);
    int* coli = (int*)(smraw + OFF_COLI);

    const int tid  = threadIdx.x;
    const int lane = tid & 31;
    const int wid  = tid >> 5;
    const int e0   = blockIdx.x * TM;
    const int wm   = (wid & 3) * 32;
    const int wn   = (wid >> 2) * 64;

    const uint32_t smbAh = smem_u32(smraw + OFF_A_HI);
    const uint32_t smbAl = smem_u32(smraw + OFF_A_LO);
    const uint32_t smbBh = smem_u32(smraw + OFF_B_HI);
    const uint32_t smbBl = smem_u32(smraw + OFF_B_LO);

    if (tid < TM) {
        int ec = min(e0 + tid, nE - 1);
        rowi[tid] = eidx[ec];
        coli[tid] = eidx[nE + ec];
    }

    // ---- load ea tile -> A hi/lo (bf16 split) ----
    {
        const int r  = tid >> 1;
        const int c0 = (tid & 1) * 64;
        const float* src = ea + (size_t)min(e0 + r, nE - 1) * H + c0;
        char* dh = smraw + OFF_A_HI + (size_t)(r * SA + c0) * 2;
        char* dl = smraw + OFF_A_LO + (size_t)(r * SA + c0) * 2;
        #pragma unroll
        for (int j = 0; j < 16; j++) {
            float4 f = *(const float4*)(src + j * 4);
            uint2 uh, ul;
            uh.x = pack2(f.x, f.y); uh.y = pack2(f.z, f.w);
            ul.x = pack2(f.x - bf_hi(f.x), f.y - bf_hi(f.y));
            ul.y = pack2(f.z - bf_hi(f.z), f.w - bf_hi(f.w));
            *(uint2*)(dh + j * 8) = uh;
            *(uint2*)(dl + j * 8) = ul;
        }
    }
    __syncthreads();

    float acc[2][8][4];
    const float* We1c = We1 + (size_t)256 * H;   // rows 256..383 (edge_attr part)

    #pragma unroll 1
    for (int stage = 0; stage < 2; stage++) {
        const float* Wst = stage ? We2 : We1c;

        #pragma unroll
        for (int mf = 0; mf < 2; mf++)
            #pragma unroll
            for (int nf = 0; nf < 8; nf++)
                #pragma unroll
                for (int c = 0; c < 4; c++) acc[mf][nf][c] = 0.f;

        #pragma unroll 1
        for (int kc = 0; kc < 2; kc++) {
            // ---- load B chunk (64 k-rows x 128 n), split hi/lo ----
            {
                const int r = tid >> 2;
                const int q = (tid & 3) * 32;
                const float* src = Wst + (size_t)(kc * 64 + r) * H + q;
                char* dh = smraw + OFF_B_HI + (size_t)(r * SB + q) * 2;
                char* dl = smraw + OFF_B_LO + (size_t)(r * SB + q) * 2;
                #pragma unroll
                for (int j = 0; j < 8; j++) {
                    float4 f = *(const float4*)(src + j * 4);
                    uint2 uh, ul;
                    uh.x = pack2(f.x, f.y); uh.y = pack2(f.z, f.w);
                    ul.x = pack2(f.x - bf_hi(f.x), f.y - bf_hi(f.y));
                    ul.y = pack2(f.z - bf_hi(f.z), f.w - bf_hi(f.w));
                    *(uint2*)(dh + j * 8) = uh;
                    *(uint2*)(dl + j * 8) = ul;
                }
            }
            __syncthreads();

            #pragma unroll
            for (int ks = 0; ks < 4; ks++) {
                const int k0 = kc * 64 + ks * 16;   // column in A
                const int kB = ks * 16;             // local row in B chunk
                uint32_t ah[2][4], al[2][4];
                #pragma unroll
                for (int mf = 0; mf < 2; mf++) {
                    uint32_t aoff = (uint32_t)((wm + mf * 16 + (lane & 15)) * SA
                                               + k0 + ((lane >> 4) << 3)) * 2;
                    LDM_X4(ah[mf], smbAh + aoff);
                    LDM_X4(al[mf], smbAl + aoff);
                }
                #pragma unroll
                for (int nf = 0; nf < 8; nf++) {
                    const uint32_t boff = (uint32_t)((kB + (lane & 15)) * SB
                                                     + wn + nf * 8) * 2;
                    uint32_t bh[2], bl[2];
                    LDM_X2T(bh, smbBh + boff);
                    LDM_X2T(bl, smbBl + boff);
                    #pragma unroll
                    for (int mf = 0; mf < 2; mf++) {
                        MMA_BF16(acc[mf][nf], ah[mf], bh);
                        MMA_BF16(acc[mf][nf], ah[mf], bl);
                        MMA_BF16(acc[mf][nf], al[mf], bh);
                    }
                }
            }
            __syncthreads();
        }

        if (stage == 0) {
            // ---- epilogue 1: + b1 + P[row] + Q[col], relu, re-split -> A ----
            float2 b1c[8];
            #pragma unroll
            for (int nf = 0; nf < 8; nf++)
                b1c[nf] = *(const float2*)(be1 + wn + nf * 8 + (lane & 3) * 2);
            #pragma unroll
            for (int mf = 0; mf < 2; mf++) {
                #pragma unroll
                for (int rh = 0; rh < 2; rh++) {
                    const int rt = wm + mf * 16 + rh * 8 + (lane >> 2);
                    const float* pP = g_P + (size_t)rowi[rt] * H;
                    const float* pQ = g_Q + (size_t)coli[rt] * H;
                    #pragma unroll
                    for (int nf = 0; nf < 8; nf++) {
                        const int col = wn + nf * 8 + (lane & 3) * 2;
                        float2 p = *(const float2*)(pP + col);
                        float2 q = *(const float2*)(pQ + col);
                        float h0 = fmaxf(acc[mf][nf][rh * 2 + 0] + p.x + q.x + b1c[nf].x, 0.f);
                        float h1 = fmaxf(acc[mf][nf][rh * 2 + 1] + p.y + q.y + b1c[nf].y, 0.f);
                        const uint32_t off = (uint32_t)(rt * SA + col) * 2;
                        *(uint32_t*)(smraw + OFF_A_HI + off) = pack2(h0, h1);
                        *(uint32_t*)(smraw + OFF_A_LO + off) =
                            pack2(h0 - bf_hi(h0), h1 - bf_hi(h1));
                    }
                }
            }
            __syncthreads();
        } else {
            // ---- epilogue 2: + b2 -> f32 staging (reuse A region) -> scatter ----
            float* msgf = (float*)(smraw + OFF_A_HI);   // [128][SF] f32 = 69632 B
            float2 b2c[8];
            #pragma unroll
            for (int nf = 0; nf < 8; nf++)
                b2c[nf] = *(const float2*)(be2 + wn + nf * 8 + (lane & 3) * 2);
            #pragma unroll
            for (int mf = 0; mf < 2; mf++) {
                #pragma unroll
                for (int rh = 0; rh < 2; rh++) {
                    const int rt = wm + mf * 16 + rh * 8 + (lane >> 2);
                    #pragma unroll
                    for (int nf = 0; nf < 8; nf++) {
                        const int col = wn + nf * 8 + (lane & 3) * 2;
                        float2 m;
                        m.x = acc[mf][nf][rh * 2 + 0] + b2c[nf].x;
                        m.y = acc[mf][nf][rh * 2 + 1] + b2c[nf].y;
                        *(float2*)(msgf + rt * SF + col) = m;
                    }
                }
            }
            __syncthreads();

            const int r  = tid >> 1;
            const int cb = (tid & 1) * 64;
            if (e0 + r < nE) {
                float* dst = g_agg + (size_t)coli[r] * H + cb;
                const float* srcm = msgf + r * SF + cb;
                #pragma unroll
                for (int j = 0; j < 16; j++) {
                    float4 m = *(const float4*)(srcm + j * 4);
                    red_add_v4(dst + j * 4, m.x, m.y, m.z, m.w);
                }
            }
        }
    }
}

// ---------------------------------------------------------------------------
// Node pass: fp32 (proven). out = MLP2(concat(x, agg))
// ---------------------------------------------------------------------------
__global__ void __launch_bounds__(NTHR, 2)
node_kernel(const float* __restrict__ x,
            const float* __restrict__ Wn1, const float* __restrict__ bn1,
            const float* __restrict__ Wn2, const float* __restrict__ bn2,
            float* __restrict__ out, int nN)
{
    extern __shared__ float sm[];
    float* Bs  = sm;
    float* Hsm = sm + KC * H;
    float* As  = Hsm + TM * (H + 4);

    const int tid = threadIdx.x;
    const int tx  = tid & 15;
    const int ty  = tid >> 4;
    const int n0  = blockIdx.x * TM;

    const int le = tid >> 1;
    const int lh = (tid & 1) * 8;
    const size_t nrow = (size_t)min(n0 + le, nN - 1) * H;
    const float* aX = x + nrow;
    const float* aG = g_agg + nrow;

    const int bk = tid >> 4;
    const int bh = (tid & 15) * 8;

    float acc[8][8];
    {
        float bj[8];
        #pragma unroll
        for (int j = 0; j < 8; j++) bj[j] = bn1[tx * 8 + j];
        #pragma unroll
        for (int i = 0; i < 8; i++)
            #pragma unroll
            for (int j = 0; j < 8; j++) acc[i][j] = bj[j];
    }

    for (int kc = 0; kc < 16; kc++) {
        const int k0 = (kc & 7) * KC;
        const float* abase = (kc < 8) ? aX : aG;
        float4 a0 = *(const float4*)(abase + k0 + lh);
        float4 a1 = *(const float4*)(abase + k0 + lh + 4);
        const float* wrow = Wn1 + (size_t)(kc * KC + bk) * H + bh;
        float4 b0 = *(const float4*)(wrow);
        float4 b1 = *(const float4*)(wrow + 4);
        __syncthreads();
        As[(lh + 0) * TM + le] = a0.x; As[(lh + 1) * TM + le] = a0.y;
        As[(lh + 2) * TM + le] = a0.z; As[(lh + 3) * TM + le] = a0.w;
        As[(lh + 4) * TM + le] = a1.x; As[(lh + 5) * TM + le] = a1.y;
        As[(lh + 6) * TM + le] = a1.z; As[(lh + 7) * TM + le] = a1.w;
        *(float4*)&Bs[bk * H + bh]     = b0;
        *(float4*)&Bs[bk * H + bh + 4] = b1;
        __syncthreads();
        #pragma unroll
        for (int kk = 0; kk < KC; kk++) {
            float af[8], bf[8];
            *(float4*)&af[0] = *(const float4*)&As[kk * TM + ty * 8];
            *(float4*)&af[4] = *(const float4*)&As[kk * TM + ty * 8 + 4];
            *(float4*)&bf[0] = *(const float4*)&Bs[kk * H + tx * 8];
            *(float4*)&bf[4] = *(const float4*)&Bs[kk * H + tx * 8 + 4];
            #pragma unroll
            for (int i = 0; i < 8; i++)
                #pragma unroll
                for (int j = 0; j < 8; j++)
                    acc[i][j] = fmaf(af[i], bf[j], acc[i][j]);
        }
    }

    __syncthreads();
    #pragma unroll
    for (int i = 0; i < 8; i++) {
        const int r = ty * 8 + i;
        float* hp = &Hsm[r * (H + 4) + tx * 8];
        float4 h0, h1;
        h0.x = fmaxf(acc[i][0], 0.f); h0.y = fmaxf(acc[i][1], 0.f);
        h0.z = fmaxf(acc[i][2], 0.f); h0.w = fmaxf(acc[i][3], 0.f);
        h1.x = fmaxf(acc[i][4], 0.f); h1.y = fmaxf(acc[i][5], 0.f);
        h1.z = fmaxf(acc[i][6], 0.f); h1.w = fmaxf(acc[i][7], 0.f);
        *(float4*)(hp)     = h0;
        *(float4*)(hp + 4) = h1;
    }
    {
        float bj[8];
        #pragma unroll
        for (int j = 0; j < 8; j++) bj[j] = bn2[tx * 8 + j];
        #pragma unroll
        for (int i = 0; i < 8; i++)
            #pragma unroll
            for (int j = 0; j < 8; j++) acc[i][j] = bj[j];
    }
    __syncthreads();

    for (int kc = 0; kc < 8; kc++) {
        const float* wrow = Wn2 + (size_t)(kc * KC + bk) * H + bh;
        float4 b0 = *(const float4*)(wrow);
        float4 b1 = *(const float4*)(wrow + 4);
        __syncthreads();
        *(float4*)&Bs[bk * H + bh]     = b0;
        *(float4*)&Bs[bk * H + bh + 4] = b1;
        __syncthreads();
        #pragma unroll
        for (int kk = 0; kk < KC; kk++) {
            const int k = kc * KC + kk;
            float bf[8];
            *(float4*)&bf[0] = *(const float4*)&Bs[kk * H + tx * 8];
            *(float4*)&bf[4] = *(const float4*)&Bs[kk * H + tx * 8 + 4];
            #pragma unroll
            for (int i = 0; i < 8; i++) {
                float a = Hsm[(ty * 8 + i) * (H + 4) + k];
                #pragma unroll
                for (int j = 0; j < 8; j++)
                    acc[i][j] = fmaf(a, bf[j], acc[i][j]);
            }
        }
    }

    #pragma unroll
    for (int i = 0; i < 8; i++) {
        const int r = ty * 8 + i;
        if (n0 + r < nN) {
            float* dst = out + (size_t)(n0 + r) * H + tx * 8;
            *(float4*)(dst)     = make_float4(acc[i][0], acc[i][1], acc[i][2], acc[i][3]);
            *(float4*)(dst + 4) = make_float4(acc[i][4], acc[i][5], acc[i][6], acc[i][7]);
        }
    }
}

extern "C" void kernel_launch(void* const* d_in, const int* in_sizes, int n_in,
                              void* d_out, int out_size)
{
    const float* x    = (const float*)d_in[0];
    const int*   eidx = (const int*)d_in[1];
    const float* ea   = (const float*)d_in[2];
    const float* We1  = (const float*)d_in[3];
    const float* be1  = (const float*)d_in[4];
    const float* We2  = (const float*)d_in[5];
    const float* be2  = (const float*)d_in[6];
    const float* Wn1  = (const float*)d_in[7];
    const float* bn1  = (const float*)d_in[8];
    const float* Wn2  = (const float*)d_in[9];
    const float* bn2  = (const float*)d_in[10];
    float* out = (float*)d_out;

    const int nN = in_sizes[0] / H;
    const int nE = in_sizes[1] / 2;

    const int node_smem = (KC * H + TM * (H + 4) + KC * TM) * (int)sizeof(float);
    const int prep_smem = (KC * H + KC * TM) * (int)sizeof(float);
    cudaFuncSetAttribute(edge_kernel, cudaFuncAttributeMaxDynamicSharedMemorySize, EDGE_SMEM);
    cudaFuncSetAttribute(node_kernel, cudaFuncAttributeMaxDynamicSharedMemorySize, node_smem);
    cudaFuncSetAttribute(prep_pq_kernel, cudaFuncAttributeMaxDynamicSharedMemorySize, prep_smem);

    const int n4 = nN * H / 4;
    zero_agg_kernel<<<(n4 + 255) / 256, 256>>>(n4);

    dim3 pq_grid((nN + TM - 1) / TM, 2);
    prep_pq_kernel<<<pq_grid, NTHR, prep_smem>>>(x, We1, nN);

    edge_kernel<<<(nE + TM - 1) / TM, NTHR, EDGE_SMEM>>>(ea, eidx, We1, be1, We2, be2, nE);
    node_kernel<<<(nN + TM - 1) / TM, NTHR, node_smem>>>(x, Wn1, bn1, Wn2, bn2, out, nN);
}